// round 11
// baseline (speedup 1.0000x reference)
#include <cuda_runtime.h>
#include <cuda_bf16.h>
#include <math.h>

#define NN   100000
#define EE   3200000
#define DIN  256
#define DHID 256
#define DOUT 64

// ---------------- scratch (__device__ globals; no allocation allowed) -------
__device__ int   g_deg[NN];
__device__ int   g_off[NN + 1];
__device__ int   g_cur[NN];
__device__ float g_dinv[NN];
__device__ int2  g_csrw[EE];   // packed (src, __float_as_int(dinv[src]))
__device__ __align__(16) __nv_bfloat16 g_h1[(size_t)NN * DHID];  // bf16 x@W1
__device__ __align__(16) __nv_bfloat16 g_a1[(size_t)NN * DHID];  // bf16 relu(agg)
__device__ __align__(16) __nv_bfloat16 g_h2[(size_t)NN * DOUT];  // bf16 a1@W2

// ---------------- helpers ----------------------------------------------------
__device__ __forceinline__ unsigned int bf2(float lo, float hi) {
    unsigned int r;
    asm("cvt.rn.bf16x2.f32 %0, %1, %2;" : "=r"(r) : "f"(hi), "f"(lo));
    return r;
}
__device__ __forceinline__ float2 ubf2f(unsigned int u) {
    return __bfloat1622float2(*reinterpret_cast<const __nv_bfloat162*>(&u));
}
__device__ __forceinline__ unsigned int smem_u32(const void* p) {
    return (unsigned int)__cvta_generic_to_shared(p);
}
__device__ __forceinline__ void ldsm_x4(unsigned int addr, unsigned int& r0,
                                        unsigned int& r1, unsigned int& r2,
                                        unsigned int& r3) {
    asm volatile("ldmatrix.sync.aligned.m8n8.x4.shared.b16 {%0,%1,%2,%3}, [%4];"
                 : "=r"(r0), "=r"(r1), "=r"(r2), "=r"(r3) : "r"(addr));
}
__device__ __forceinline__ void ldsm_x4t(unsigned int addr, unsigned int& r0,
                                         unsigned int& r1, unsigned int& r2,
                                         unsigned int& r3) {
    asm volatile("ldmatrix.sync.aligned.m8n8.x4.trans.shared.b16 {%0,%1,%2,%3}, [%4];"
                 : "=r"(r0), "=r"(r1), "=r"(r2), "=r"(r3) : "r"(addr));
}
__device__ __forceinline__ void mma_bf16(float c[4],
                                         unsigned int a0, unsigned int a1,
                                         unsigned int a2, unsigned int a3,
                                         unsigned int b0, unsigned int b1) {
    asm volatile(
        "mma.sync.aligned.m16n8k16.row.col.f32.bf16.bf16.f32 "
        "{%0,%1,%2,%3},{%4,%5,%6,%7},{%8,%9},{%0,%1,%2,%3};"
        : "+f"(c[0]), "+f"(c[1]), "+f"(c[2]), "+f"(c[3])
        : "r"(a0), "r"(a1), "r"(a2), "r"(a3), "r"(b0), "r"(b1));
}

// ---------------- degree / CSR build -----------------------------------------
extern "C" __global__ __launch_bounds__(256) void k_count(const int* dst, int e) {
    for (int i = blockIdx.x * blockDim.x + threadIdx.x; i < e;
         i += gridDim.x * blockDim.x)
        atomicAdd(&g_deg[dst[i]], 1);
}

// scan + dinv fused (final loop touches every node anyway)
extern "C" __global__ __launch_bounds__(1024) void k_scan() {
    __shared__ int partial[1024];
    int t = threadIdx.x;
    const int CH = (NN + 1023) / 1024;
    int start = t * CH;
    int end   = start + CH; if (end > NN) end = NN;
    int s = 0;
    for (int i = start; i < end; i++) s += g_deg[i];
    partial[t] = s;
    __syncthreads();
    for (int d = 1; d < 1024; d <<= 1) {
        int v = (t >= d) ? partial[t - d] : 0;
        __syncthreads();
        partial[t] += v;
        __syncthreads();
    }
    int run = (t > 0) ? partial[t - 1] : 0;
    for (int i = start; i < end; i++) {
        g_off[i] = run;
        g_cur[i] = run;
        int dg = g_deg[i];
        g_dinv[i] = rsqrtf((float)(dg + 1));   // +1 self-loop
        run += dg;
    }
    if (t == 1023) g_off[NN] = partial[1023];
}

// fill packed (src, dinv[src]) pairs
extern "C" __global__ __launch_bounds__(256) void k_fill(const int* src,
                                                         const int* dst, int e) {
    for (int i = blockIdx.x * blockDim.x + threadIdx.x; i < e;
         i += gridDim.x * blockDim.x) {
        int s = src[i];
        int p = atomicAdd(&g_cur[dst[i]], 1);
        g_csrw[p] = make_int2(s, __float_as_int(g_dinv[s]));
    }
}

// ---------------- GEMM 1 (tensor core): g_h1(bf16) = x @ W1 ------------------
#define AP1 24    // A smem row pitch (bf16): 16 data + 8 pad
#define BP1 264   // B smem row pitch (bf16): 256 data + 8 pad
extern "C" __global__ __launch_bounds__(256) void k_gemm1(
    const float* __restrict__ A, const float* __restrict__ B) {
    __shared__ __align__(16) __nv_bfloat16 Asm[128 * AP1];
    __shared__ __align__(16) __nv_bfloat16 Bsm[16 * BP1];
    const int tid  = threadIdx.x;
    const int wid  = tid >> 5;
    const int lane = tid & 31;
    const int m0   = blockIdx.x * 128;
    const int wm   = (wid & 1) * 64;
    const int wn   = (wid >> 1) * 64;

    float c[4][8][4];
#pragma unroll
    for (int i = 0; i < 4; i++)
#pragma unroll
        for (int j = 0; j < 8; j++)
#pragma unroll
            for (int q = 0; q < 4; q++) c[i][j][q] = 0.f;

    for (int k0 = 0; k0 < DIN; k0 += 16) {
#pragma unroll
        for (int i = 0; i < 2; i++) {
            int idx = tid + i * 256;
            int row = idx >> 2;
            int kq  = (idx & 3) * 4;
            int gm  = m0 + row;
            float4 v = make_float4(0.f, 0.f, 0.f, 0.f);
            if (gm < NN) v = *(const float4*)(A + (size_t)gm * DIN + k0 + kq);
            *(uint2*)&Asm[row * AP1 + kq] = make_uint2(bf2(v.x, v.y), bf2(v.z, v.w));
        }
#pragma unroll
        for (int i = 0; i < 4; i++) {
            int idx = tid + i * 256;
            int kr  = idx >> 6;
            int nc  = (idx & 63) * 4;
            float4 v = *(const float4*)(B + (size_t)(k0 + kr) * DHID + nc);
            *(uint2*)&Bsm[kr * BP1 + nc] = make_uint2(bf2(v.x, v.y), bf2(v.z, v.w));
        }
        __syncthreads();

        unsigned int a[4][4];
#pragma unroll
        for (int ms = 0; ms < 4; ms++) {
            int row = wm + ms * 16 + (lane & 15);
            int col = (lane >> 4) * 8;
            ldsm_x4(smem_u32(&Asm[row * AP1 + col]),
                    a[ms][0], a[ms][1], a[ms][2], a[ms][3]);
        }
        unsigned int b[8][2];
#pragma unroll
        for (int nt = 0; nt < 4; nt++) {
            int k  = lane & 15;
            int nb = wn + nt * 16 + (lane >> 4) * 8;
            ldsm_x4t(smem_u32(&Bsm[k * BP1 + nb]),
                     b[2 * nt][0], b[2 * nt][1], b[2 * nt + 1][0], b[2 * nt + 1][1]);
        }
#pragma unroll
        for (int ms = 0; ms < 4; ms++)
#pragma unroll
            for (int ns = 0; ns < 8; ns++)
                mma_bf16(c[ms][ns], a[ms][0], a[ms][1], a[ms][2], a[ms][3],
                         b[ns][0], b[ns][1]);
        __syncthreads();
    }
#pragma unroll
    for (int ms = 0; ms < 4; ms++) {
        int r0 = m0 + wm + ms * 16 + (lane >> 2);
        int r1 = r0 + 8;
#pragma unroll
        for (int ns = 0; ns < 8; ns++) {
            int col = wn + ns * 8 + (lane & 3) * 2;
            if (r0 < NN)
                *(unsigned int*)(g_h1 + (size_t)r0 * DHID + col) =
                    bf2(c[ms][ns][0], c[ms][ns][1]);
            if (r1 < NN)
                *(unsigned int*)(g_h1 + (size_t)r1 * DHID + col) =
                    bf2(c[ms][ns][2], c[ms][ns][3]);
        }
    }
}

// ---------------- GEMM 2 (tensor core): g_h2(bf16) = g_a1(bf16) @ W2 ---------
#define BP2 72
extern "C" __global__ __launch_bounds__(128) void k_gemm2(
    const float* __restrict__ B) {
    __shared__ __align__(16) __nv_bfloat16 Asm[128 * AP1];
    __shared__ __align__(16) __nv_bfloat16 Bsm[16 * BP2];
    const int tid  = threadIdx.x;
    const int wid  = tid >> 5;
    const int lane = tid & 31;
    const int m0   = blockIdx.x * 128;
    const int wm   = (wid & 1) * 64;
    const int wn   = (wid >> 1) * 32;

    float c[4][4][4];
#pragma unroll
    for (int i = 0; i < 4; i++)
#pragma unroll
        for (int j = 0; j < 4; j++)
#pragma unroll
            for (int q = 0; q < 4; q++) c[i][j][q] = 0.f;

    for (int k0 = 0; k0 < DHID; k0 += 16) {
#pragma unroll
        for (int i = 0; i < 2; i++) {
            int idx  = tid + i * 128;
            int row  = idx >> 1;
            int half = (idx & 1) * 8;
            int gm   = m0 + row;
            uint4 v = make_uint4(0u, 0u, 0u, 0u);
            if (gm < NN) v = *(const uint4*)(g_a1 + (size_t)gm * DHID + k0 + half);
            *(uint4*)&Asm[row * AP1 + half] = v;
        }
#pragma unroll
        for (int i = 0; i < 2; i++) {
            int idx = tid + i * 128;
            int kr  = idx >> 4;
            int nc  = (idx & 15) * 4;
            float4 v = *(const float4*)(B + (size_t)(k0 + kr) * DOUT + nc);
            *(uint2*)&Bsm[kr * BP2 + nc] = make_uint2(bf2(v.x, v.y), bf2(v.z, v.w));
        }
        __syncthreads();

        unsigned int a[4][4];
#pragma unroll
        for (int ms = 0; ms < 4; ms++) {
            int row = wm + ms * 16 + (lane & 15);
            int col = (lane >> 4) * 8;
            ldsm_x4(smem_u32(&Asm[row * AP1 + col]),
                    a[ms][0], a[ms][1], a[ms][2], a[ms][3]);
        }
        unsigned int b[4][2];
#pragma unroll
        for (int nt = 0; nt < 2; nt++) {
            int k  = lane & 15;
            int nb = wn + nt * 16 + (lane >> 4) * 8;
            ldsm_x4t(smem_u32(&Bsm[k * BP2 + nb]),
                     b[2 * nt][0], b[2 * nt][1], b[2 * nt + 1][0], b[2 * nt + 1][1]);
        }
#pragma unroll
        for (int ms = 0; ms < 4; ms++)
#pragma unroll
            for (int ns = 0; ns < 4; ns++)
                mma_bf16(c[ms][ns], a[ms][0], a[ms][1], a[ms][2], a[ms][3],
                         b[ns][0], b[ns][1]);
        __syncthreads();
    }
#pragma unroll
    for (int ms = 0; ms < 4; ms++) {
        int r0 = m0 + wm + ms * 16 + (lane >> 2);
        int r1 = r0 + 8;
#pragma unroll
        for (int ns = 0; ns < 4; ns++) {
            int col = wn + ns * 8 + (lane & 3) * 2;
            if (r0 < NN)
                *(unsigned int*)(g_h2 + (size_t)r0 * DOUT + col) =
                    bf2(c[ms][ns][0], c[ms][ns][1]);
            if (r1 < NN)
                *(unsigned int*)(g_h2 + (size_t)r1 * DOUT + col) =
                    bf2(c[ms][ns][2], c[ms][ns][3]);
        }
    }
}

// ---------------- layer-1 aggregation: one warp per dst, unroll-4 ------------
__device__ __forceinline__ void acc_row1(float acc[8], float ws, uint4 v) {
    const unsigned int* u = (const unsigned int*)&v;
#pragma unroll
    for (int q = 0; q < 4; q++) {
        float2 f = ubf2f(u[q]);
        acc[2 * q]     = fmaf(ws, f.x, acc[2 * q]);
        acc[2 * q + 1] = fmaf(ws, f.y, acc[2 * q + 1]);
    }
}

extern "C" __global__ __launch_bounds__(256) void k_agg1(const float* __restrict__ b1) {
    int lane = threadIdx.x & 31;
    int warps = (gridDim.x * blockDim.x) >> 5;
    for (int w = (blockIdx.x * blockDim.x + threadIdx.x) >> 5; w < NN; w += warps) {
        float di = g_dinv[w];
        float acc[8];
        {
            uint4 v = __ldg(&((const uint4*)(g_h1 + (size_t)w * DHID))[lane]);
            const unsigned int* u = (const unsigned int*)&v;
#pragma unroll
            for (int q = 0; q < 4; q++) {
                float2 f = ubf2f(u[q]);
                acc[2 * q]     = di * f.x;
                acc[2 * q + 1] = di * f.y;
            }
        }
        int e   = g_off[w];
        int end = g_off[w + 1];
        for (; e + 4 <= end; e += 4) {
            int2 p0 = __ldg(&g_csrw[e]);
            int2 p1 = __ldg(&g_csrw[e + 1]);
            int2 p2 = __ldg(&g_csrw[e + 2]);
            int2 p3 = __ldg(&g_csrw[e + 3]);
            uint4 v0 = __ldg(&((const uint4*)(g_h1 + (size_t)p0.x * DHID))[lane]);
            uint4 v1 = __ldg(&((const uint4*)(g_h1 + (size_t)p1.x * DHID))[lane]);
            uint4 v2 = __ldg(&((const uint4*)(g_h1 + (size_t)p2.x * DHID))[lane]);
            uint4 v3 = __ldg(&((const uint4*)(g_h1 + (size_t)p3.x * DHID))[lane]);
            acc_row1(acc, __int_as_float(p0.y), v0);
            acc_row1(acc, __int_as_float(p1.y), v1);
            acc_row1(acc, __int_as_float(p2.y), v2);
            acc_row1(acc, __int_as_float(p3.y), v3);
        }
        for (; e < end; e++) {
            int2 p = __ldg(&g_csrw[e]);
            uint4 v = __ldg(&((const uint4*)(g_h1 + (size_t)p.x * DHID))[lane]);
            acc_row1(acc, __int_as_float(p.y), v);
        }
        float4 bb0 = ((const float4*)b1)[lane * 2];
        float4 bb1 = ((const float4*)b1)[lane * 2 + 1];
        uint4 pk;
        pk.x = bf2(fmaxf(di * acc[0] + bb0.x, 0.f), fmaxf(di * acc[1] + bb0.y, 0.f));
        pk.y = bf2(fmaxf(di * acc[2] + bb0.z, 0.f), fmaxf(di * acc[3] + bb0.w, 0.f));
        pk.z = bf2(fmaxf(di * acc[4] + bb1.x, 0.f), fmaxf(di * acc[5] + bb1.y, 0.f));
        pk.w = bf2(fmaxf(di * acc[6] + bb1.z, 0.f), fmaxf(di * acc[7] + bb1.w, 0.f));
        ((uint4*)(g_a1 + (size_t)w * DHID))[lane] = pk;
    }
}

// ---------------- layer-2 aggregation + bias + log_softmax, unroll-4 ---------
extern "C" __global__ __launch_bounds__(256) void k_agg2(const float* __restrict__ b2,
                                                         float* __restrict__ out) {
    int lane = threadIdx.x & 31;
    int warps = (gridDim.x * blockDim.x) >> 5;
    for (int w = (blockIdx.x * blockDim.x + threadIdx.x) >> 5; w < NN; w += warps) {
        float di = g_dinv[w];
        float ax, ay;
        {
            unsigned int v = __ldg(&((const unsigned int*)(g_h2 + (size_t)w * DOUT))[lane]);
            float2 f = ubf2f(v);
            ax = di * f.x;
            ay = di * f.y;
        }
        int e   = g_off[w];
        int end = g_off[w + 1];
        for (; e + 4 <= end; e += 4) {
            int2 p0 = __ldg(&g_csrw[e]);
            int2 p1 = __ldg(&g_csrw[e + 1]);
            int2 p2 = __ldg(&g_csrw[e + 2]);
            int2 p3 = __ldg(&g_csrw[e + 3]);
            unsigned int v0 = __ldg(&((const unsigned int*)(g_h2 + (size_t)p0.x * DOUT))[lane]);
            unsigned int v1 = __ldg(&((const unsigned int*)(g_h2 + (size_t)p1.x * DOUT))[lane]);
            unsigned int v2 = __ldg(&((const unsigned int*)(g_h2 + (size_t)p2.x * DOUT))[lane]);
            unsigned int v3 = __ldg(&((const unsigned int*)(g_h2 + (size_t)p3.x * DOUT))[lane]);
            float2 f0 = ubf2f(v0), f1 = ubf2f(v1), f2 = ubf2f(v2), f3 = ubf2f(v3);
            float w0 = __int_as_float(p0.y), w1 = __int_as_float(p1.y);
            float w2 = __int_as_float(p2.y), w3 = __int_as_float(p3.y);
            ax = fmaf(w0, f0.x, ax); ay = fmaf(w0, f0.y, ay);
            ax = fmaf(w1, f1.x, ax); ay = fmaf(w1, f1.y, ay);
            ax = fmaf(w2, f2.x, ax); ay = fmaf(w2, f2.y, ay);
            ax = fmaf(w3, f3.x, ax); ay = fmaf(w3, f3.y, ay);
        }
        for (; e < end; e++) {
            int2 p = __ldg(&g_csrw[e]);
            unsigned int v = __ldg(&((const unsigned int*)(g_h2 + (size_t)p.x * DOUT))[lane]);
            float2 f = ubf2f(v);
            float ws = __int_as_float(p.y);
            ax = fmaf(ws, f.x, ax);
            ay = fmaf(ws, f.y, ay);
        }
        float2 bb = ((const float2*)b2)[lane];
        float zx = di * ax + bb.x;
        float zy = di * ay + bb.y;
        float m = fmaxf(zx, zy);
#pragma unroll
        for (int o = 16; o; o >>= 1) m = fmaxf(m, __shfl_xor_sync(0xffffffffu, m, o));
        float s = expf(zx - m) + expf(zy - m);
#pragma unroll
        for (int o = 16; o; o >>= 1) s += __shfl_xor_sync(0xffffffffu, s, o);
        float lse = m + logf(s);
        float2 r; r.x = zx - lse; r.y = zy - lse;
        ((float2*)(out + (size_t)w * DOUT))[lane] = r;
    }
}

// ---------------- launch ------------------------------------------------------
extern "C" void kernel_launch(void* const* d_in, const int* in_sizes, int n_in,
                              void* d_out, int out_size) {
    // Identify inputs by element count — all six counts are distinct.
    const float* x  = nullptr;
    const int*   ei = nullptr;
    const float* W1 = nullptr;
    const float* b1 = nullptr;
    const float* W2 = nullptr;
    const float* b2 = nullptr;
    for (int i = 0; i < n_in; i++) {
        switch (in_sizes[i]) {
            case NN * DIN:    x  = (const float*)d_in[i]; break;  // 25600000
            case 2 * EE:      ei = (const int*)d_in[i];   break;  //  6400000
            case DIN * DHID:  W1 = (const float*)d_in[i]; break;  //    65536
            case DHID:        b1 = (const float*)d_in[i]; break;  //      256
            case DHID * DOUT: W2 = (const float*)d_in[i]; break;  //    16384
            case DOUT:        b2 = (const float*)d_in[i]; break;  //       64
            default: break;
        }
    }
    float* out = (float*)d_out;
    const int* src = ei;        // row-major (2, E): row 0 = src, row 1 = dst
    const int* dst = ei + EE;

    // Only g_deg needs zeroing.
    int* p_deg;  cudaGetSymbolAddress((void**)&p_deg, g_deg);
    cudaMemsetAsync(p_deg, 0, NN * sizeof(int));

    // CSR build (count -> scan+dinv -> fill-packed)
    k_count<<<2048, 256>>>(dst, EE);
    k_scan<<<1, 1024>>>();
    k_fill<<<2048, 256>>>(src, dst, EE);

    // layer 1
    k_gemm1<<<(NN + 127) / 128, 256>>>(x, W1);
    k_agg1<<<12500, 256>>>(b1);

    // layer 2
    k_gemm2<<<(NN + 127) / 128, 128>>>(W2);
    k_agg2<<<12500, 256>>>(b2, out);
}